// round 8
// baseline (speedup 1.0000x reference)
#include <cuda_runtime.h>
#include <cuda_fp16.h>

// GRU autoencoder, SEQ_LEN=4096, fp16-compressed streamed weights, fp32 math.
// e1: 1 -> 2048, e2: 2048 -> 1024 (pipelined, 1 grid-sync/step)
// d1: 1024 -> 1024 (constant input => xg precomputed), d2: 1024 -> 2048 (pipelined)
// head: 2048 -> 1
// R7: back to 512 thr + unroll-4 (best base). Balance fix: block-level weighted
//     static partition + intra-block dynamic item queue (smem atomic counter).

#define TT    4096
#define H1    2048     // e1 / d2 hidden
#define H2    1024     // e2 / d1 hidden
#define NTHR  512
#define WPB   (NTHR >> 5)

// ---------------- device scratch ----------------------------------------------
__device__ float g_h1[2][H1];        // e1 state, double buffered by time parity
__device__ float g_h2[2][H2];        // e2 state
__device__ float g_hd1[2][H2];       // d1 state
__device__ float g_xgd1[3 * H2];     // constant input-gate preactivation for d1
__device__ float g_ys3[TT][H1];      // d2 outputs (also d2 state history)

// fp16 copies of the streamed weight matrices (converted on every launch)
__device__ __align__(16) __half c_w1hh[3 * H1 * H1];   // 25.2 MB
__device__ __align__(16) __half c_w2ih[3 * H2 * H1];   // 12.6 MB
__device__ __align__(16) __half c_w2hh[3 * H2 * H2];   //  6.3 MB
__device__ __align__(16) __half c_d1hh[3 * H2 * H2];   //  6.3 MB
__device__ __align__(16) __half c_d2ih[3 * H1 * H2];   // 12.6 MB
__device__ __align__(16) __half c_d2hh[3 * H1 * H1];   // 25.2 MB

__device__ __align__(128) unsigned int g_barcnt[32];   // zero-init; self-resetting
__device__ __align__(128) unsigned int g_bargen[32];

// ---------------- helpers -----------------------------------------------------
__device__ __forceinline__ float warp_red(float v) {
    v += __shfl_down_sync(0xffffffffu, v, 16);
    v += __shfl_down_sync(0xffffffffu, v, 8);
    v += __shfl_down_sync(0xffffffffu, v, 4);
    v += __shfl_down_sync(0xffffffffu, v, 2);
    v += __shfl_down_sync(0xffffffffu, v, 1);
    return v;
}

// Software grid barrier; generation-relative so it survives graph replays.
__device__ __forceinline__ void gridsync(int nblk) {
    __threadfence();
    __syncthreads();
    if (threadIdx.x == 0) {
        volatile unsigned int* gen = &g_bargen[0];
        unsigned int g = *gen;
        if (atomicAdd(&g_barcnt[0], 1u) == (unsigned)(nblk - 1)) {
            g_barcnt[0] = 0;
            __threadfence();
            *gen = g + 1;
        } else {
            while (*gen == g) { }
        }
        __threadfence();
    }
    __syncthreads();
}

__device__ __forceinline__ void acc8(float& a, const uint4& r,
                                     const float4& vA, const float4& vB) {
    float2 f;
    f = __half22float2(*reinterpret_cast<const __half2*>(&r.x));
    a = fmaf(f.x, vA.x, a); a = fmaf(f.y, vA.y, a);
    f = __half22float2(*reinterpret_cast<const __half2*>(&r.y));
    a = fmaf(f.x, vA.z, a); a = fmaf(f.y, vA.w, a);
    f = __half22float2(*reinterpret_cast<const __half2*>(&r.z));
    a = fmaf(f.x, vB.x, a); a = fmaf(f.y, vB.y, a);
    f = __half22float2(*reinterpret_cast<const __half2*>(&r.w));
    a = fmaf(f.x, vB.z, a); a = fmaf(f.y, vB.w, a);
}

// 3 simultaneous dot products (r/z/n gate rows, fp16 weights) against an
// fp32 shared-memory vector. Lane-strided: 8 halfs / lane / chunk.
// Unroll 4 => up to 12 LDG.128 batched per warp to cover L2 latency.
template <int L>
__device__ __forceinline__ void dot3h(const __half* __restrict__ w0,
                                      const __half* __restrict__ w1,
                                      const __half* __restrict__ w2,
                                      const float* __restrict__ sv,
                                      int lane, float& d0, float& d1, float& d2) {
    float a0 = 0.f, a1 = 0.f, a2 = 0.f;
#pragma unroll 4
    for (int j = 0; j < L / 256; ++j) {
        const int idx = j * 256 + lane * 8;
        const uint4 r0 = __ldg(reinterpret_cast<const uint4*>(w0 + idx));
        const uint4 r1 = __ldg(reinterpret_cast<const uint4*>(w1 + idx));
        const uint4 r2 = __ldg(reinterpret_cast<const uint4*>(w2 + idx));
        const float4 vA = *reinterpret_cast<const float4*>(sv + idx);
        const float4 vB = *reinterpret_cast<const float4*>(sv + idx + 4);
        acc8(a0, r0, vA, vB);
        acc8(a1, r1, vA, vB);
        acc8(a2, r2, vA, vB);
    }
    d0 = warp_red(a0);
    d1 = warp_red(a1);
    d2 = warp_red(a2);
}

__device__ __forceinline__ float sigf(float v) { return 1.f / (1.f + expf(-v)); }

// ---------------- fp32 -> fp16 weight conversion ------------------------------
__global__ void f2h_kernel(const float* __restrict__ src, __half* __restrict__ dst, int n) {
    const int stride = gridDim.x * blockDim.x * 8;
    for (int i = (blockIdx.x * blockDim.x + threadIdx.x) * 8; i < n; i += stride) {
        const float4 a = __ldg(reinterpret_cast<const float4*>(src + i));
        const float4 b = __ldg(reinterpret_cast<const float4*>(src + i + 4));
        const __half2 h0 = __floats2half2_rn(a.x, a.y);
        const __half2 h1 = __floats2half2_rn(a.z, a.w);
        const __half2 h2 = __floats2half2_rn(b.x, b.y);
        const __half2 h3 = __floats2half2_rn(b.z, b.w);
        uint4 o;
        o.x = *reinterpret_cast<const unsigned int*>(&h0);
        o.y = *reinterpret_cast<const unsigned int*>(&h1);
        o.z = *reinterpret_cast<const unsigned int*>(&h2);
        o.w = *reinterpret_cast<const unsigned int*>(&h3);
        *reinterpret_cast<uint4*>(dst + i) = o;
    }
}

// Weighted item-boundary maps (weight space -> item index), encoder:
// items 0..2047 = e1 rows (weight 2), items 2048..3071 = e2 rows (weight 3).
__device__ __forceinline__ int enc_f(long long w) {
    return (w <= 4096) ? (int)((w + 1) >> 1)
                       : 2048 + (int)((w - 4096 + 2) / 3);
}
// decoder: items 0..1023 = d1 rows (weight 1), 1024..3071 = d2 rows (weight 3).
__device__ __forceinline__ int dec_f(long long w) {
    return (w <= 1024) ? (int)w
                       : 1024 + (int)((w - 1024 + 2) / 3);
}

// ---------------- encoder: e1 (1->2048) + e2 (2048->1024), pipelined ----------
__global__ void __launch_bounds__(NTHR, 1) gru_encoder(
    const float* __restrict__ x,
    const float* __restrict__ w1ih, const float* __restrict__ b1ih,
    const float* __restrict__ b1hh,
    const float* __restrict__ b2ih, const float* __restrict__ b2hh,
    int nblk)
{
    __shared__ __align__(16) float s_h1[H1];   // h1(t-1) == ys1(t-1)
    __shared__ __align__(16) float s_h2[H2];   // h2(t-2)
    __shared__ int s_next;
    const int tid  = threadIdx.x;
    const int lane = tid & 31;
    const long long Q = 7168;

    // Block-level weighted static partition (±6% balance at block granularity).
    const int itemLo = enc_f((long long)blockIdx.x * Q / nblk);
    const int itemHi = (blockIdx.x == nblk - 1) ? (H1 + H2)
                       : enc_f((long long)(blockIdx.x + 1) * Q / nblk);

    // Iter t: layer1 computes h1(t) (t<TT); layer2 computes h2(t-1) (t>=1).
    for (int t = 0; t <= TT; ++t) {
        const float* h1p = g_h1[(t + 1) & 1];   // parity of (t-1)
        for (int i = tid * 4; i < H1; i += NTHR * 4) {
            float4 v = (t == 0) ? make_float4(0.f, 0.f, 0.f, 0.f)
                                : __ldcg(reinterpret_cast<const float4*>(h1p + i));
            *reinterpret_cast<float4*>(s_h1 + i) = v;
        }
        const float* h2p = g_h2[t & 1];          // parity of (t-2)
        for (int i = tid * 4; i < H2; i += NTHR * 4) {
            float4 v = (t <= 1) ? make_float4(0.f, 0.f, 0.f, 0.f)
                                : __ldcg(reinterpret_cast<const float4*>(h2p + i));
            *reinterpret_cast<float4*>(s_h2 + i) = v;
        }
        if (tid == 0) s_next = itemLo;
        __syncthreads();

        const float xt = (t < TT) ? __ldg(x + t) : 0.f;

        // Intra-block dynamic item queue: warps grab whole items. Each item is
        // computed entirely (fixed summation order) by one warp -> deterministic.
        for (;;) {
            int k;
            if (lane == 0) k = atomicAdd(&s_next, 1);
            k = __shfl_sync(0xffffffffu, k, 0);
            if (k >= itemHi) break;

            if (k < H1) {
                if (t == TT) continue;
                const int i = k;
                float hr, hz, hn;
                dot3h<H1>(c_w1hh + (size_t)i * H1,
                          c_w1hh + (size_t)(i + H1) * H1,
                          c_w1hh + (size_t)(i + 2 * H1) * H1,
                          s_h1, lane, hr, hz, hn);
                if (lane == 0) {
                    const float xr = fmaf(xt, __ldg(w1ih + i),          __ldg(b1ih + i));
                    const float xz = fmaf(xt, __ldg(w1ih + i + H1),     __ldg(b1ih + i + H1));
                    const float xn = fmaf(xt, __ldg(w1ih + i + 2 * H1), __ldg(b1ih + i + 2 * H1));
                    hr += __ldg(b1hh + i);
                    hz += __ldg(b1hh + i + H1);
                    hn += __ldg(b1hh + i + 2 * H1);
                    const float r = sigf(xr + hr);
                    const float z = sigf(xz + hz);
                    const float n = tanhf(xn + r * hn);
                    g_h1[t & 1][i] = (1.f - z) * n + z * s_h1[i];
                }
            } else {
                if (t == 0) continue;
                const int i = k - H1;     // e2 output index, computing h2(t-1)
                float xr, xz, xn, hr, hz, hn;
                dot3h<H1>(c_w2ih + (size_t)i * H1,
                          c_w2ih + (size_t)(i + H2) * H1,
                          c_w2ih + (size_t)(i + 2 * H2) * H1,
                          s_h1, lane, xr, xz, xn);             // input = ys1(t-1)
                dot3h<H2>(c_w2hh + (size_t)i * H2,
                          c_w2hh + (size_t)(i + H2) * H2,
                          c_w2hh + (size_t)(i + 2 * H2) * H2,
                          s_h2, lane, hr, hz, hn);
                if (lane == 0) {
                    xr += __ldg(b2ih + i);
                    xz += __ldg(b2ih + i + H2);
                    xn += __ldg(b2ih + i + 2 * H2);
                    hr += __ldg(b2hh + i);
                    hz += __ldg(b2hh + i + H2);
                    hn += __ldg(b2hh + i + 2 * H2);
                    const float r = sigf(xr + hr);
                    const float z = sigf(xz + hz);
                    const float n = tanhf(xn + r * hn);
                    g_h2[(t + 1) & 1][i] = (1.f - z) * n + z * s_h2[i]; // parity of (t-1)
                }
            }
        }
        gridsync(nblk);
    }
}

// ---------------- d1 constant input-gate preactivation ------------------------
// emb = final h2 = h2(TT-1), stored at parity (TT-1)&1 == 1.
__global__ void gru_xgd1(const float* __restrict__ d1ih,
                         const float* __restrict__ d1bih)
{
    const int lane = threadIdx.x & 31;
    const int gw = blockIdx.x * (blockDim.x >> 5) + (threadIdx.x >> 5);
    const int nw = gridDim.x * (blockDim.x >> 5);
    for (int j = gw; j < 3 * H2; j += nw) {
        float a = 0.f;
        const float* w = d1ih + (size_t)j * H2;
#pragma unroll 4
        for (int q = 0; q < H2 / 128; ++q) {
            const int idx = q * 128 + lane * 4;
            const float4 r = __ldg(reinterpret_cast<const float4*>(w + idx));
            const float4 v = __ldcg(reinterpret_cast<const float4*>(&g_h2[1][idx]));
            a = fmaf(r.x, v.x, a); a = fmaf(r.y, v.y, a);
            a = fmaf(r.z, v.z, a); a = fmaf(r.w, v.w, a);
        }
        a = warp_red(a);
        if (lane == 0) g_xgd1[j] = a + __ldg(d1bih + j);
    }
}

// ---------------- decoder: d1 (const in ->1024) + d2 (1024->2048), pipelined --
__global__ void __launch_bounds__(NTHR, 1) gru_decoder(
    const float* __restrict__ b1hh,
    const float* __restrict__ b2ih, const float* __restrict__ b2hh,
    int nblk)
{
    __shared__ __align__(16) float s_d1[H2];   // hd1(t-1) == ys2(t-1)
    __shared__ __align__(16) float s_y3[H1];   // ys3(t-2) == hd2 prev state
    __shared__ int s_next;
    const int tid  = threadIdx.x;
    const int lane = tid & 31;
    const long long Q = 7168;

    const int itemLo = dec_f((long long)blockIdx.x * Q / nblk);
    const int itemHi = (blockIdx.x == nblk - 1) ? (H2 + H1)
                       : dec_f((long long)(blockIdx.x + 1) * Q / nblk);

    for (int t = 0; t <= TT; ++t) {
        const int s = t - 1;                    // d2 computes ys3[s]
        const float* d1p = g_hd1[(t + 1) & 1];
        for (int i = tid * 4; i < H2; i += NTHR * 4) {
            float4 v = (t == 0) ? make_float4(0.f, 0.f, 0.f, 0.f)
                                : __ldcg(reinterpret_cast<const float4*>(d1p + i));
            *reinterpret_cast<float4*>(s_d1 + i) = v;
        }
        for (int i = tid * 4; i < H1; i += NTHR * 4) {
            float4 v = (t <= 1) ? make_float4(0.f, 0.f, 0.f, 0.f)
                                : __ldcg(reinterpret_cast<const float4*>(&g_ys3[s - 1][i]));
            *reinterpret_cast<float4*>(s_y3 + i) = v;
        }
        if (tid == 0) s_next = itemLo;
        __syncthreads();

        for (;;) {
            int k;
            if (lane == 0) k = atomicAdd(&s_next, 1);
            k = __shfl_sync(0xffffffffu, k, 0);
            if (k >= itemHi) break;

            if (k < H2) {
                if (t == TT) continue;
                const int i = k;                // d1 output, computing hd1(t)
                float hr, hz, hn;
                dot3h<H2>(c_d1hh + (size_t)i * H2,
                          c_d1hh + (size_t)(i + H2) * H2,
                          c_d1hh + (size_t)(i + 2 * H2) * H2,
                          s_d1, lane, hr, hz, hn);
                if (lane == 0) {
                    const float xr = g_xgd1[i];             // includes bih
                    const float xz = g_xgd1[i + H2];
                    const float xn = g_xgd1[i + 2 * H2];
                    hr += __ldg(b1hh + i);
                    hz += __ldg(b1hh + i + H2);
                    hn += __ldg(b1hh + i + 2 * H2);
                    const float r = sigf(xr + hr);
                    const float z = sigf(xz + hz);
                    const float n = tanhf(xn + r * hn);
                    g_hd1[t & 1][i] = (1.f - z) * n + z * s_d1[i];
                }
            } else {
                if (t == 0) continue;
                const int i = k - H2;           // d2 output, computing ys3[s]
                float xr, xz, xn, hr, hz, hn;
                dot3h<H2>(c_d2ih + (size_t)i * H2,
                          c_d2ih + (size_t)(i + H1) * H2,
                          c_d2ih + (size_t)(i + 2 * H1) * H2,
                          s_d1, lane, xr, xz, xn);           // input = ys2(s)
                dot3h<H1>(c_d2hh + (size_t)i * H1,
                          c_d2hh + (size_t)(i + H1) * H1,
                          c_d2hh + (size_t)(i + 2 * H1) * H1,
                          s_y3, lane, hr, hz, hn);
                if (lane == 0) {
                    xr += __ldg(b2ih + i);
                    xz += __ldg(b2ih + i + H1);
                    xn += __ldg(b2ih + i + 2 * H1);
                    hr += __ldg(b2hh + i);
                    hz += __ldg(b2hh + i + H1);
                    hn += __ldg(b2hh + i + 2 * H1);
                    const float r = sigf(xr + hr);
                    const float z = sigf(xz + hz);
                    const float n = tanhf(xn + r * hn);
                    g_ys3[s][i] = (1.f - z) * n + z * s_y3[i];
                }
            }
        }
        gridsync(nblk);
    }
}

// ---------------- output head: out[t] = ys3[t] . out_W + out_b ----------------
__global__ void gru_output(const float* __restrict__ ow,
                           const float* __restrict__ ob,
                           float* __restrict__ out)
{
    const int lane = threadIdx.x & 31;
    const int gw = blockIdx.x * (blockDim.x >> 5) + (threadIdx.x >> 5);
    const int nw = gridDim.x * (blockDim.x >> 5);
    for (int t = gw; t < TT; t += nw) {
        float a = 0.f;
#pragma unroll 4
        for (int q = 0; q < H1 / 128; ++q) {
            const int idx = q * 128 + lane * 4;
            const float4 w = __ldg(reinterpret_cast<const float4*>(ow + idx));
            const float4 v = *reinterpret_cast<const float4*>(&g_ys3[t][idx]);
            a = fmaf(w.x, v.x, a); a = fmaf(w.y, v.y, a);
            a = fmaf(w.z, v.z, a); a = fmaf(w.w, v.w, a);
        }
        a = warp_red(a);
        if (lane == 0) out[t] = a + __ldg(ob);
    }
}

// ---------------- launch ------------------------------------------------------
extern "C" void kernel_launch(void* const* d_in, const int* in_sizes, int n_in,
                              void* d_out, int out_size) {
    const float* x      = (const float*)d_in[0];
    const float* e1_Wih = (const float*)d_in[1];
    const float* e1_Whh = (const float*)d_in[2];
    const float* e1_bih = (const float*)d_in[3];
    const float* e1_bhh = (const float*)d_in[4];
    const float* e2_Wih = (const float*)d_in[5];
    const float* e2_Whh = (const float*)d_in[6];
    const float* e2_bih = (const float*)d_in[7];
    const float* e2_bhh = (const float*)d_in[8];
    const float* d1_Wih = (const float*)d_in[9];
    const float* d1_Whh = (const float*)d_in[10];
    const float* d1_bih = (const float*)d_in[11];
    const float* d1_bhh = (const float*)d_in[12];
    const float* d2_Wih = (const float*)d_in[13];
    const float* d2_Whh = (const float*)d_in[14];
    const float* d2_bih = (const float*)d_in[15];
    const float* d2_bhh = (const float*)d_in[16];
    const float* out_W  = (const float*)d_in[17];
    const float* out_b  = (const float*)d_in[18];

    int nblk = 148;
    cudaDeviceGetAttribute(&nblk, cudaDevAttrMultiProcessorCount, 0);

    __half* p_w1hh; cudaGetSymbolAddress((void**)&p_w1hh, c_w1hh);
    __half* p_w2ih; cudaGetSymbolAddress((void**)&p_w2ih, c_w2ih);
    __half* p_w2hh; cudaGetSymbolAddress((void**)&p_w2hh, c_w2hh);
    __half* p_d1hh; cudaGetSymbolAddress((void**)&p_d1hh, c_d1hh);
    __half* p_d2ih; cudaGetSymbolAddress((void**)&p_d2ih, c_d2ih);
    __half* p_d2hh; cudaGetSymbolAddress((void**)&p_d2hh, c_d2hh);

    f2h_kernel<<<512, 256>>>(e1_Whh, p_w1hh, 3 * H1 * H1);
    f2h_kernel<<<512, 256>>>(e2_Wih, p_w2ih, 3 * H2 * H1);
    f2h_kernel<<<512, 256>>>(e2_Whh, p_w2hh, 3 * H2 * H2);
    f2h_kernel<<<512, 256>>>(d1_Whh, p_d1hh, 3 * H2 * H2);
    f2h_kernel<<<512, 256>>>(d2_Wih, p_d2ih, 3 * H1 * H2);
    f2h_kernel<<<512, 256>>>(d2_Whh, p_d2hh, 3 * H1 * H1);

    gru_encoder<<<nblk, NTHR>>>(x, e1_Wih, e1_bih, e1_bhh, e2_bih, e2_bhh, nblk);
    gru_xgd1<<<96, 256>>>(d1_Wih, d1_bih);
    gru_decoder<<<nblk, NTHR>>>(d1_bhh, d2_bih, d2_bhh, nblk);
    gru_output<<<256, 256>>>(out_W, out_b, (float*)d_out);
}

// round 9
// speedup vs baseline: 1.0212x; 1.0212x over previous
#include <cuda_runtime.h>
#include <cuda_fp16.h>

// GRU autoencoder, SEQ_LEN=4096. fp16 weights, fp32 math.
// R8: SMEM-resident layer weights. Encoder streams only e1_Whh (25.2 MB/step,
// one 12KB row per warp, 14 warps/block => perfectly uniform); e2 weights
// (18.9 MB) live in each block's SMEM (128 KB/block), chewed by warps 14-15.
// Decoder symmetric: stream d2_Whh, SMEM-resident d2_Wih + d1_Whh.

#define TT    4096
#define H1    2048     // e1 / d2 hidden
#define H2    1024     // e2 / d1 hidden
#define NTHR  512
#define EW    14       // streaming warps per block (1 uniform row each)

// ---------------- device scratch ----------------------------------------------
__device__ float g_h1[2][H1];        // e1 state, double buffered by time parity
__device__ float g_h2[2][H2];        // e2 state
__device__ float g_hd1[2][H2];       // d1 state
__device__ float g_xgd1[3 * H2];     // constant input-gate preactivation for d1
__device__ float g_ys3[TT][H1];      // d2 outputs (also d2 state history)

// fp16 copies of the STREAMED weight matrices only
__device__ __align__(16) __half c_w1hh[3 * H1 * H1];   // 25.2 MB
__device__ __align__(16) __half c_d2hh[3 * H1 * H1];   // 25.2 MB

__device__ __align__(128) unsigned int g_barcnt[32];   // zero-init; self-resetting
__device__ __align__(128) unsigned int g_bargen[32];

// ---------------- helpers -----------------------------------------------------
__device__ __forceinline__ float warp_red(float v) {
    v += __shfl_down_sync(0xffffffffu, v, 16);
    v += __shfl_down_sync(0xffffffffu, v, 8);
    v += __shfl_down_sync(0xffffffffu, v, 4);
    v += __shfl_down_sync(0xffffffffu, v, 2);
    v += __shfl_down_sync(0xffffffffu, v, 1);
    return v;
}

__device__ __forceinline__ void gridsync(int nblk) {
    __threadfence();
    __syncthreads();
    if (threadIdx.x == 0) {
        volatile unsigned int* gen = &g_bargen[0];
        unsigned int g = *gen;
        if (atomicAdd(&g_barcnt[0], 1u) == (unsigned)(nblk - 1)) {
            g_barcnt[0] = 0;
            __threadfence();
            *gen = g + 1;
        } else {
            while (*gen == g) { }
        }
        __threadfence();
    }
    __syncthreads();
}

__device__ __forceinline__ void acc8(float& a, const uint4& r,
                                     const float4& vA, const float4& vB) {
    float2 f;
    f = __half22float2(*reinterpret_cast<const __half2*>(&r.x));
    a = fmaf(f.x, vA.x, a); a = fmaf(f.y, vA.y, a);
    f = __half22float2(*reinterpret_cast<const __half2*>(&r.y));
    a = fmaf(f.x, vA.z, a); a = fmaf(f.y, vA.w, a);
    f = __half22float2(*reinterpret_cast<const __half2*>(&r.z));
    a = fmaf(f.x, vB.x, a); a = fmaf(f.y, vB.y, a);
    f = __half22float2(*reinterpret_cast<const __half2*>(&r.w));
    a = fmaf(f.x, vB.z, a); a = fmaf(f.y, vB.w, a);
}

// 3 dot products (r/z/n gates) with GLOBAL fp16 weights vs SMEM fp32 vector.
template <int L>
__device__ __forceinline__ void dot3h(const __half* __restrict__ w0,
                                      const __half* __restrict__ w1,
                                      const __half* __restrict__ w2,
                                      const float* __restrict__ sv,
                                      int lane, float& d0, float& d1, float& d2) {
    float a0 = 0.f, a1 = 0.f, a2 = 0.f;
#pragma unroll 4
    for (int j = 0; j < L / 256; ++j) {
        const int idx = j * 256 + lane * 8;
        const uint4 r0 = __ldg(reinterpret_cast<const uint4*>(w0 + idx));
        const uint4 r1 = __ldg(reinterpret_cast<const uint4*>(w1 + idx));
        const uint4 r2 = __ldg(reinterpret_cast<const uint4*>(w2 + idx));
        const float4 vA = *reinterpret_cast<const float4*>(sv + idx);
        const float4 vB = *reinterpret_cast<const float4*>(sv + idx + 4);
        acc8(a0, r0, vA, vB);
        acc8(a1, r1, vA, vB);
        acc8(a2, r2, vA, vB);
    }
    d0 = warp_red(a0);
    d1 = warp_red(a1);
    d2 = warp_red(a2);
}

// 3 dot products with SMEM fp16 weights vs SMEM fp32 vector.
template <int L>
__device__ __forceinline__ void dot3s(const __half* __restrict__ w0,
                                      const __half* __restrict__ w1,
                                      const __half* __restrict__ w2,
                                      const float* __restrict__ sv,
                                      int lane, float& d0, float& d1, float& d2) {
    float a0 = 0.f, a1 = 0.f, a2 = 0.f;
#pragma unroll 4
    for (int j = 0; j < L / 256; ++j) {
        const int idx = j * 256 + lane * 8;
        const uint4 r0 = *reinterpret_cast<const uint4*>(w0 + idx);
        const uint4 r1 = *reinterpret_cast<const uint4*>(w1 + idx);
        const uint4 r2 = *reinterpret_cast<const uint4*>(w2 + idx);
        const float4 vA = *reinterpret_cast<const float4*>(sv + idx);
        const float4 vB = *reinterpret_cast<const float4*>(sv + idx + 4);
        acc8(a0, r0, vA, vB);
        acc8(a1, r1, vA, vB);
        acc8(a2, r2, vA, vB);
    }
    d0 = warp_red(a0);
    d1 = warp_red(a1);
    d2 = warp_red(a2);
}

__device__ __forceinline__ float sigf(float v) { return 1.f / (1.f + expf(-v)); }

// ---------------- fp32 -> fp16 weight conversion (streamed matrices) ----------
__global__ void f2h_kernel(const float* __restrict__ src, __half* __restrict__ dst, int n) {
    const int stride = gridDim.x * blockDim.x * 8;
    for (int i = (blockIdx.x * blockDim.x + threadIdx.x) * 8; i < n; i += stride) {
        const float4 a = __ldg(reinterpret_cast<const float4*>(src + i));
        const float4 b = __ldg(reinterpret_cast<const float4*>(src + i + 4));
        const __half2 h0 = __floats2half2_rn(a.x, a.y);
        const __half2 h1 = __floats2half2_rn(a.z, a.w);
        const __half2 h2 = __floats2half2_rn(b.x, b.y);
        const __half2 h3 = __floats2half2_rn(b.z, b.w);
        uint4 o;
        o.x = *reinterpret_cast<const unsigned int*>(&h0);
        o.y = *reinterpret_cast<const unsigned int*>(&h1);
        o.z = *reinterpret_cast<const unsigned int*>(&h2);
        o.w = *reinterpret_cast<const unsigned int*>(&h3);
        *reinterpret_cast<uint4*>(dst + i) = o;
    }
}

// ---------------- encoder -----------------------------------------------------
// Warps 0..EW-1: one e1 row each (global id blockIdx*EW+wid), streaming c_w1hh.
// Warps EW..15: this block's e2 rows [rlo,rhi) from SMEM-resident weights.
// SMEM e2 row layout (9216 halfs): ih_r(2048) ih_z ih_n | hh_r(1024) hh_z hh_n.
__global__ void __launch_bounds__(NTHR, 1) gru_encoder(
    const float* __restrict__ x,
    const float* __restrict__ w1ih, const float* __restrict__ b1ih,
    const float* __restrict__ b1hh,
    const float* __restrict__ w2ih, const float* __restrict__ w2hh,
    const float* __restrict__ b2ih, const float* __restrict__ b2hh,
    int nblk)
{
    extern __shared__ __align__(16) float smem[];
    float* s_h1 = smem;                 // h1(t-1)
    float* s_h2 = smem + H1;            // h2(t-2)
    __half* s_w = reinterpret_cast<__half*>(smem + H1 + H2);

    const int tid  = threadIdx.x;
    const int lane = tid & 31;
    const int wid  = tid >> 5;

    const int rlo = blockIdx.x * H2 / nblk;
    const int rhi = (blockIdx.x + 1) * H2 / nblk;
    const int nr  = rhi - rlo;

    // Preload this block's e2 weights into SMEM (fp32 inputs -> fp16).
    for (int idx = tid; idx < nr * 9216; idx += NTHR) {
        const int r = idx / 9216;
        const int p = idx - r * 9216;
        const int i = rlo + r;
        float v;
        if (p < 6144) {
            const int g = p >> 11, c = p & 2047;
            v = __ldg(w2ih + (size_t)(i + g * H2) * H1 + c);
        } else {
            const int q = p - 6144;
            const int g = q >> 10, c = q & 1023;
            v = __ldg(w2hh + (size_t)(i + g * H2) * H2 + c);
        }
        s_w[idx] = __float2half_rn(v);
    }
    __syncthreads();

    const int e1row = blockIdx.x * EW + wid;          // valid if wid<EW && <H1
    // e2 rows split between warps EW and EW+1
    const int halfn = (nr + 1) >> 1;
    const int er0 = (wid == EW) ? 0 : halfn;
    const int er1 = (wid == EW) ? halfn : nr;

    for (int t = 0; t <= TT; ++t) {
        const float* h1p = g_h1[(t + 1) & 1];         // parity of (t-1)
        for (int i = tid * 4; i < H1; i += NTHR * 4) {
            float4 v = (t == 0) ? make_float4(0.f, 0.f, 0.f, 0.f)
                                : __ldcg(reinterpret_cast<const float4*>(h1p + i));
            *reinterpret_cast<float4*>(s_h1 + i) = v;
        }
        const float* h2p = g_h2[t & 1];               // parity of (t-2)
        for (int i = tid * 4; i < H2; i += NTHR * 4) {
            float4 v = (t <= 1) ? make_float4(0.f, 0.f, 0.f, 0.f)
                                : __ldcg(reinterpret_cast<const float4*>(h2p + i));
            *reinterpret_cast<float4*>(s_h2 + i) = v;
        }
        __syncthreads();

        if (wid < EW) {
            if (t < TT && e1row < H1) {
                const int i = e1row;
                const float xt = __ldg(x + t);
                float hr, hz, hn;
                dot3h<H1>(c_w1hh + (size_t)i * H1,
                          c_w1hh + (size_t)(i + H1) * H1,
                          c_w1hh + (size_t)(i + 2 * H1) * H1,
                          s_h1, lane, hr, hz, hn);
                if (lane == 0) {
                    const float xr = fmaf(xt, __ldg(w1ih + i),          __ldg(b1ih + i));
                    const float xz = fmaf(xt, __ldg(w1ih + i + H1),     __ldg(b1ih + i + H1));
                    const float xn = fmaf(xt, __ldg(w1ih + i + 2 * H1), __ldg(b1ih + i + 2 * H1));
                    hr += __ldg(b1hh + i);
                    hz += __ldg(b1hh + i + H1);
                    hn += __ldg(b1hh + i + 2 * H1);
                    const float r = sigf(xr + hr);
                    const float z = sigf(xz + hz);
                    const float n = tanhf(xn + r * hn);
                    g_h1[t & 1][i] = (1.f - z) * n + z * s_h1[i];
                }
            }
        } else if (t >= 1) {
            for (int r = er0; r < er1; ++r) {         // computing h2(t-1)
                const int i = rlo + r;
                const __half* base = s_w + (size_t)r * 9216;
                float xr, xz, xn, hr, hz, hn;
                dot3s<H1>(base, base + 2048, base + 4096, s_h1, lane, xr, xz, xn);
                dot3s<H2>(base + 6144, base + 7168, base + 8192, s_h2, lane, hr, hz, hn);
                if (lane == 0) {
                    xr += __ldg(b2ih + i);
                    xz += __ldg(b2ih + i + H2);
                    xn += __ldg(b2ih + i + 2 * H2);
                    hr += __ldg(b2hh + i);
                    hz += __ldg(b2hh + i + H2);
                    hn += __ldg(b2hh + i + 2 * H2);
                    const float rr = sigf(xr + hr);
                    const float zz = sigf(xz + hz);
                    const float nn = tanhf(xn + rr * hn);
                    g_h2[(t + 1) & 1][i] = (1.f - zz) * nn + zz * s_h2[i];
                }
            }
        }
        gridsync(nblk);
    }
}

// ---------------- d1 constant input-gate preactivation ------------------------
// emb = final h2 = h2(TT-1), stored at parity (TT-1)&1 == 1.
__global__ void gru_xgd1(const float* __restrict__ d1ih,
                         const float* __restrict__ d1bih)
{
    const int lane = threadIdx.x & 31;
    const int gw = blockIdx.x * (blockDim.x >> 5) + (threadIdx.x >> 5);
    const int nw = gridDim.x * (blockDim.x >> 5);
    for (int j = gw; j < 3 * H2; j += nw) {
        float a = 0.f;
        const float* w = d1ih + (size_t)j * H2;
#pragma unroll 4
        for (int q = 0; q < H2 / 128; ++q) {
            const int idx = q * 128 + lane * 4;
            const float4 r = __ldg(reinterpret_cast<const float4*>(w + idx));
            const float4 v = __ldcg(reinterpret_cast<const float4*>(&g_h2[1][idx]));
            a = fmaf(r.x, v.x, a); a = fmaf(r.y, v.y, a);
            a = fmaf(r.z, v.z, a); a = fmaf(r.w, v.w, a);
        }
        a = warp_red(a);
        if (lane == 0) g_xgd1[j] = a + __ldg(d1bih + j);
    }
}

// ---------------- decoder -----------------------------------------------------
// Warps 0..EW-1: one d2 row each; stream c_d2hh (12 KB), d2-ih from SMEM.
// Warps EW..15: this block's d1 rows from SMEM.
// SMEM layout: d2-ih slabs (EW rows x 3072 halfs) then d1 slabs (nd1 x 3072).
__global__ void __launch_bounds__(NTHR, 1) gru_decoder(
    const float* __restrict__ b1hh,
    const float* __restrict__ d2ih, const float* __restrict__ b2ih,
    const float* __restrict__ b2hh,
    const float* __restrict__ d1hh,
    int nblk)
{
    extern __shared__ __align__(16) float smem[];
    float* s_d1 = smem;                 // hd1(t-1) == ys2(t-1)
    float* s_y3 = smem + H2;            // ys3(t-2)
    __half* s_w = reinterpret_cast<__half*>(smem + H1 + H2);

    const int tid  = threadIdx.x;
    const int lane = tid & 31;
    const int wid  = tid >> 5;

    const int d1lo = blockIdx.x * H2 / nblk;
    const int d1hi = (blockIdx.x + 1) * H2 / nblk;
    const int nd1  = d1hi - d1lo;

    // Preload: d2-ih rows for this block's EW streamed rows, then d1 rows.
    const int totalH = EW * 3072 + nd1 * 3072;
    for (int idx = tid; idx < totalH; idx += NTHR) {
        float v = 0.f;
        if (idx < EW * 3072) {
            const int r = idx / 3072;
            const int p = idx - r * 3072;
            const int i = blockIdx.x * EW + r;
            if (i < H1) {
                const int g = p >> 10, c = p & 1023;
                v = __ldg(d2ih + (size_t)(i + g * H1) * H2 + c);
            }
        } else {
            const int idx2 = idx - EW * 3072;
            const int r = idx2 / 3072;
            const int p = idx2 - r * 3072;
            const int i = d1lo + r;
            const int g = p >> 10, c = p & 1023;
            v = __ldg(d1hh + (size_t)(i + g * H2) * H2 + c);
        }
        s_w[idx] = __float2half_rn(v);
    }
    __syncthreads();

    const int d2row = blockIdx.x * EW + wid;
    const int halfn = (nd1 + 1) >> 1;
    const int dr0 = (wid == EW) ? 0 : halfn;
    const int dr1 = (wid == EW) ? halfn : nd1;

    for (int t = 0; t <= TT; ++t) {
        const int s = t - 1;                          // d2 computes ys3[s]
        const float* d1p = g_hd1[(t + 1) & 1];
        for (int i = tid * 4; i < H2; i += NTHR * 4) {
            float4 v = (t == 0) ? make_float4(0.f, 0.f, 0.f, 0.f)
                                : __ldcg(reinterpret_cast<const float4*>(d1p + i));
            *reinterpret_cast<float4*>(s_d1 + i) = v;
        }
        for (int i = tid * 4; i < H1; i += NTHR * 4) {
            float4 v = (t <= 1) ? make_float4(0.f, 0.f, 0.f, 0.f)
                                : __ldcg(reinterpret_cast<const float4*>(&g_ys3[s - 1][i]));
            *reinterpret_cast<float4*>(s_y3 + i) = v;
        }
        __syncthreads();

        if (wid < EW) {
            if (t >= 1 && d2row < H1) {
                const int i = d2row;
                const __half* base = s_w + (size_t)wid * 3072;
                float xr, xz, xn, hr, hz, hn;
                dot3s<H2>(base, base + 1024, base + 2048, s_d1, lane, xr, xz, xn);
                dot3h<H1>(c_d2hh + (size_t)i * H1,
                          c_d2hh + (size_t)(i + H1) * H1,
                          c_d2hh + (size_t)(i + 2 * H1) * H1,
                          s_y3, lane, hr, hz, hn);
                if (lane == 0) {
                    xr += __ldg(b2ih + i);
                    xz += __ldg(b2ih + i + H1);
                    xn += __ldg(b2ih + i + 2 * H1);
                    hr += __ldg(b2hh + i);
                    hz += __ldg(b2hh + i + H1);
                    hn += __ldg(b2hh + i + 2 * H1);
                    const float r = sigf(xr + hr);
                    const float z = sigf(xz + hz);
                    const float n = tanhf(xn + r * hn);
                    g_ys3[s][i] = (1.f - z) * n + z * s_y3[i];
                }
            }
        } else if (t < TT) {
            for (int r = dr0; r < dr1; ++r) {         // d1: computing hd1(t)
                const int i = d1lo + r;
                const __half* base = s_w + (size_t)(EW + r) * 3072;
                float hr, hz, hn;
                dot3s<H2>(base, base + 1024, base + 2048, s_d1, lane, hr, hz, hn);
                if (lane == 0) {
                    const float xr = g_xgd1[i];       // includes bih
                    const float xz = g_xgd1[i + H2];
                    const float xn = g_xgd1[i + 2 * H2];
                    const float hrb = hr + __ldg(b1hh + i);
                    const float hzb = hz + __ldg(b1hh + i + H2);
                    const float hnb = hn + __ldg(b1hh + i + 2 * H2);
                    const float rr = sigf(xr + hrb);
                    const float zz = sigf(xz + hzb);
                    const float nn = tanhf(xn + rr * hnb);
                    g_hd1[t & 1][i] = (1.f - zz) * nn + zz * s_d1[i];
                }
            }
        }
        gridsync(nblk);
    }
}

// ---------------- output head: out[t] = ys3[t] . out_W + out_b ----------------
__global__ void gru_output(const float* __restrict__ ow,
                           const float* __restrict__ ob,
                           float* __restrict__ out)
{
    const int lane = threadIdx.x & 31;
    const int gw = blockIdx.x * (blockDim.x >> 5) + (threadIdx.x >> 5);
    const int nw = gridDim.x * (blockDim.x >> 5);
    for (int t = gw; t < TT; t += nw) {
        float a = 0.f;
#pragma unroll 4
        for (int q = 0; q < H1 / 128; ++q) {
            const int idx = q * 128 + lane * 4;
            const float4 w = __ldg(reinterpret_cast<const float4*>(ow + idx));
            const float4 v = *reinterpret_cast<const float4*>(&g_ys3[t][idx]);
            a = fmaf(w.x, v.x, a); a = fmaf(w.y, v.y, a);
            a = fmaf(w.z, v.z, a); a = fmaf(w.w, v.w, a);
        }
        a = warp_red(a);
        if (lane == 0) out[t] = a + __ldg(ob);
    }
}

// ---------------- launch ------------------------------------------------------
extern "C" void kernel_launch(void* const* d_in, const int* in_sizes, int n_in,
                              void* d_out, int out_size) {
    const float* x      = (const float*)d_in[0];
    const float* e1_Wih = (const float*)d_in[1];
    const float* e1_Whh = (const float*)d_in[2];
    const float* e1_bih = (const float*)d_in[3];
    const float* e1_bhh = (const float*)d_in[4];
    const float* e2_Wih = (const float*)d_in[5];
    const float* e2_Whh = (const float*)d_in[6];
    const float* e2_bih = (const float*)d_in[7];
    const float* e2_bhh = (const float*)d_in[8];
    const float* d1_Wih = (const float*)d_in[9];
    const float* d1_Whh = (const float*)d_in[10];
    const float* d1_bih = (const float*)d_in[11];
    const float* d1_bhh = (const float*)d_in[12];
    const float* d2_Wih = (const float*)d_in[13];
    const float* d2_Whh = (const float*)d_in[14];
    const float* d2_bih = (const float*)d_in[15];
    const float* d2_bhh = (const float*)d_in[16];
    const float* out_W  = (const float*)d_in[17];
    const float* out_b  = (const float*)d_in[18];

    int nblk = 148;
    cudaDeviceGetAttribute(&nblk, cudaDevAttrMultiProcessorCount, 0);

    const int nrMax  = (H2 + nblk - 1) / nblk;                 // e2/d1 rows per block
    const int smemE  = (H1 + H2) * 4 + nrMax * 9216 * 2;       // ~141 KB
    const int smemD  = (H1 + H2) * 4 + (EW + nrMax) * 3072 * 2;

    cudaFuncSetAttribute(gru_encoder, cudaFuncAttributeMaxDynamicSharedMemorySize, smemE);
    cudaFuncSetAttribute(gru_decoder, cudaFuncAttributeMaxDynamicSharedMemorySize, smemD);

    __half* p_w1hh; cudaGetSymbolAddress((void**)&p_w1hh, c_w1hh);
    __half* p_d2hh; cudaGetSymbolAddress((void**)&p_d2hh, c_d2hh);

    f2h_kernel<<<512, 256>>>(e1_Whh, p_w1hh, 3 * H1 * H1);
    f2h_kernel<<<512, 256>>>(d2_Whh, p_d2hh, 3 * H1 * H1);

    gru_encoder<<<nblk, NTHR, smemE>>>(x, e1_Wih, e1_bih, e1_bhh,
                                       e2_Wih, e2_Whh, e2_bih, e2_bhh, nblk);
    gru_xgd1<<<96, 256>>>(d1_Wih, d1_bih);
    gru_decoder<<<nblk, NTHR, smemD>>>(d1_bhh, d2_Wih, d2_bih, d2_bhh, d1_Whh, nblk);
    gru_output<<<256, 256>>>(out_W, out_b, (float*)d_out);
}